// round 1
// baseline (speedup 1.0000x reference)
#include <cuda_runtime.h>
#include <cstddef>

// Problem constants
constexpr int B      = 2;
constexpr int H      = 64;
constexpr int W      = 64;
constexpr int C      = 128;
constexpr int PH     = H / 2;           // 32
constexpr int PW     = W / 2;           // 32
constexpr int NPOOL  = PH * PW * C;     // 131072
constexpr int NOUT   = 32;
constexpr long long NIN = (long long)H * W * C;        // 524288
constexpr long long WZ  = (long long)B * NIN * NOUT;   // 33554432 elems per w_zero tensor

// Output layout (concatenated flatten of the returned tuple):
//   [0, WZ)                : w_zero (upper)      -> zeros
//   [WZ, WZ+64)            : b_out_u_  (B,1,32)
//   [WZ+64, 2*WZ+64)       : w_zero (lower)      -> zeros
//   [2*WZ+64, 2*WZ+128)    : b_out_l_  (B,1,32)
constexpr long long OFF_BU = WZ;
constexpr long long OFF_W2 = WZ + 64;
constexpr long long OFF_BL = 2 * WZ + 64;

constexpr int TILE_P  = 1024;
constexpr int NCHUNK  = NPOOL / TILE_P;  // 128
constexpr int THREADS = 256;
constexpr int NWARP   = THREADS / 32;    // 8

// Deterministic two-stage reduction scratch (no dynamic allocation allowed)
__device__ float g_scratch_u[B * NCHUNK * NOUT];
__device__ float g_scratch_l[B * NCHUNK * NOUT];

__global__ __launch_bounds__(THREADS)
void reduce_kernel(const float* __restrict__ uc,
                   const float* __restrict__ lc,
                   const float* __restrict__ wu,
                   const float* __restrict__ wl)
{
    __shared__ float s_bu[TILE_P];
    __shared__ float s_bl[TILE_P];
    __shared__ float r_u[NWARP][NOUT];
    __shared__ float r_l[NWARP][NOUT];

    const int chunk = blockIdx.x;
    const int b     = blockIdx.y;
    const int p0    = chunk * TILE_P;
    const int t     = threadIdx.x;

    // ---- Phase 1: 2x2 maxpool for this tile's pool positions -> smem ----
    const float* ucb = uc + (size_t)b * H * W * C;
    const float* lcb = lc + (size_t)b * H * W * C;
    #pragma unroll
    for (int i = t; i < TILE_P; i += THREADS) {
        const int p  = p0 + i;
        const int c  = p & (C - 1);
        const int pw = (p >> 7) & (PW - 1);
        const int ph = p >> 12;
        const int base = ((2 * ph) * W + 2 * pw) * C + c;
        // neighbors: (+0), w+1 (+C), h+1 (+W*C), h+1,w+1 (+W*C+C)
        float u0 = ucb[base];
        float u1 = ucb[base + C];
        float u2 = ucb[base + W * C];
        float u3 = ucb[base + W * C + C];
        float l0 = lcb[base];
        float l1 = lcb[base + C];
        float l2 = lcb[base + W * C];
        float l3 = lcb[base + W * C + C];
        s_bu[i] = fmaxf(fmaxf(u0, u1), fmaxf(u2, u3));
        s_bl[i] = fmaxf(fmaxf(l0, l1), fmaxf(l2, l3));
    }
    __syncthreads();

    // ---- Phase 2: warp-lane-per-output reduction over tile ----
    const int warp = t >> 5;
    const int lane = t & 31;
    float au = 0.0f, al = 0.0f;

    const float* wub = wu + ((size_t)b * NPOOL + p0) * NOUT + lane;
    const float* wlb = wl + ((size_t)b * NPOOL + p0) * NOUT + lane;

    #pragma unroll 4
    for (int i = warp; i < TILE_P; i += NWARP) {
        const float vu = wub[(size_t)i * NOUT];
        const float vl = wlb[(size_t)i * NOUT];
        const float bu = s_bu[i];
        const float bl = s_bl[i];
        au += fmaxf(vu, 0.0f) * bu + fminf(vu, 0.0f) * bl;
        al += fmaxf(vl, 0.0f) * bl + fminf(vl, 0.0f) * bu;
    }

    r_u[warp][lane] = au;
    r_l[warp][lane] = al;
    __syncthreads();

    if (warp == 0) {
        float su = 0.0f, sl = 0.0f;
        #pragma unroll
        for (int k = 0; k < NWARP; k++) {
            su += r_u[k][lane];
            sl += r_l[k][lane];
        }
        g_scratch_u[(b * NCHUNK + chunk) * NOUT + lane] = su;
        g_scratch_l[(b * NCHUNK + chunk) * NOUT + lane] = sl;
    }
}

__global__ void finalize_kernel(const float* __restrict__ bu_bias,
                                const float* __restrict__ bl_bias,
                                float* __restrict__ out)
{
    const int b = blockIdx.x;
    const int j = threadIdx.x;   // 0..31
    float su = bu_bias[b * NOUT + j];
    float sl = bl_bias[b * NOUT + j];
    #pragma unroll 8
    for (int k = 0; k < NCHUNK; k++) {
        su += g_scratch_u[(b * NCHUNK + k) * NOUT + j];
        sl += g_scratch_l[(b * NCHUNK + k) * NOUT + j];
    }
    out[OFF_BU + b * NOUT + j] = su;
    out[OFF_BL + b * NOUT + j] = sl;
}

extern "C" void kernel_launch(void* const* d_in, const int* in_sizes, int n_in,
                              void* d_out, int out_size)
{
    // metadata order: y, x_0, u_c, l_c, w_out_u, b_out_u, w_out_l, b_out_l
    const float* uc = (const float*)d_in[2];
    const float* lc = (const float*)d_in[3];
    const float* wu = (const float*)d_in[4];
    const float* bu = (const float*)d_in[5];
    const float* wl = (const float*)d_in[6];
    const float* bl = (const float*)d_in[7];
    float* out = (float*)d_out;

    // Zero the two w_zero regions (268 MB total — the dominant cost)
    cudaMemsetAsync(out,           0, (size_t)WZ * sizeof(float));
    cudaMemsetAsync(out + OFF_W2,  0, (size_t)WZ * sizeof(float));

    dim3 grid(NCHUNK, B);
    reduce_kernel<<<grid, THREADS>>>(uc, lc, wu, wl);
    finalize_kernel<<<B, NOUT>>>(bu, bl, out);
}